// round 8
// baseline (speedup 1.0000x reference)
#include <cuda_runtime.h>
#include <cuda_fp16.h>
#include <cstdint>

#define BB 4
#define SS 4096
#define DD 64
#define QT 128
#define KT 128
#define NTH 256
#define NCHUNK (SS / KT)
#define VSTR 72    // fp16 elems per V smem row (144B, conflict-free ldmatrix)
#define WSTR 136   // fp16 elems per w smem row (272B, conflict-free ldmatrix)

#define TILE_BYTES (QT * VSTR * 2)
#define BUF_BYTES  (2 * TILE_BYTES)
#define SMEM_P1    (2 * BUF_BYTES)                    // 73728
#define SMEM_P2    (QT * WSTR * 2 + KT * VSTR * 2)    // 34816 + 18432 = 53248

#define GROWS (BB * SS)

// per-row softmax stats scratch
__device__ float g_rowm[GROWS];
__device__ float g_rowz[GROWS];

#define NEGINF __int_as_float(0xff800000)

static __device__ __forceinline__ uint32_t smem_u32(const void* p) {
    uint32_t a;
    asm("{ .reg .u64 t; cvta.to.shared.u64 t, %1; cvt.u32.u64 %0, t; }" : "=r"(a) : "l"(p));
    return a;
}

static __device__ __forceinline__ uint32_t pack_f16(float lo, float hi) {
    uint32_t r;
    asm("cvt.rn.f16x2.f32 %0, %1, %2;" : "=r"(r) : "f"(hi), "f"(lo));
    return r;
}

#define LDSM4(r, a) \
    asm volatile("ldmatrix.sync.aligned.m8n8.x4.shared.b16 {%0,%1,%2,%3}, [%4];" \
                 : "=r"((r)[0]), "=r"((r)[1]), "=r"((r)[2]), "=r"((r)[3]) : "r"(a))

#define LDSM4T(r, a) \
    asm volatile("ldmatrix.sync.aligned.m8n8.x4.trans.shared.b16 {%0,%1,%2,%3}, [%4];" \
                 : "=r"((r)[0]), "=r"((r)[1]), "=r"((r)[2]), "=r"((r)[3]) : "r"(a))

static __device__ __forceinline__ void mma16816(float* d, const uint32_t* a,
                                                uint32_t b0, uint32_t b1) {
    asm volatile(
        "mma.sync.aligned.m16n8k16.row.col.f32.f16.f16.f32 "
        "{%0,%1,%2,%3}, {%4,%5,%6,%7}, {%8,%9}, {%0,%1,%2,%3};"
        : "+f"(d[0]), "+f"(d[1]), "+f"(d[2]), "+f"(d[3])
        : "r"(a[0]), "r"(a[1]), "r"(a[2]), "r"(a[3]), "r"(b0), "r"(b1));
}

// split fp32x4 -> hi/lo fp16x2 pairs into the H/L tiles
static __device__ __forceinline__ void split_store(char* smbase, uint32_t off,
                                                   float4 v) {
    __half hx = __float2half_rn(v.x);
    __half hy = __float2half_rn(v.y);
    __half hz = __float2half_rn(v.z);
    __half hw = __float2half_rn(v.w);
    uint2 H, L;
    H.x = pack_f16(v.x, v.y);
    H.y = pack_f16(v.z, v.w);
    L.x = pack_f16(v.x - __half2float(hx), v.y - __half2float(hy));
    L.y = pack_f16(v.z - __half2float(hz), v.w - __half2float(hw));
    *(uint2*)(smbase + off)              = H;
    *(uint2*)(smbase + off + TILE_BYTES) = L;
}

// ============ PASS 1: GEMM1 + raw scores + (m, Z) ============
__global__ void __launch_bounds__(NTH, 1)
attn_pass1(const float* __restrict__ Q, const float* __restrict__ V,
           float* __restrict__ attn_out)
{
    extern __shared__ __align__(16) char smraw[];   // [buf0 H|L][buf1 H|L]

    const int tid  = threadIdx.x;
    const int w    = tid >> 5;
    const int lane = tid & 31;
    const int g    = lane >> 2;
    const int p    = lane & 3;
    const int b    = blockIdx.y;
    const int q0   = blockIdx.x * QT;

    const float* Qg = Q + (size_t)(b * SS + q0) * DD;
    const float* Vg = V + (size_t)b * SS * DD;

    const uint32_t sbase = smem_u32(smraw);

    const int ldq  = tid >> 4;
    const int ldd4 = (tid & 15) * 4;
    const uint32_t stoff = (uint32_t)(ldq * VSTR + ldd4) * 2;

    // ---- stage Q -> buf0 hi/lo ----
    #pragma unroll
    for (int r = 0; r < 8; r++) {
        int lin = tid + r * NTH;
        int q  = lin >> 4;
        int d4 = (lin & 15) * 4;
        float4 v = *(const float4*)(Qg + q * DD + d4);
        split_store(smraw, (uint32_t)(q * VSTR + d4) * 2, v);
    }
    __syncthreads();

    const int rA = (lane & 7) + ((lane >> 3) & 1) * 8;
    const int kA = (lane >> 4) * 8;
    const int rB = (lane & 7) + (lane >> 4) * 8;
    const int kB = ((lane >> 3) & 1) * 8;

    uint32_t qh[4][4], ql[4][4];
    #pragma unroll
    for (int ks = 0; ks < 4; ks++) {
        uint32_t off = (uint32_t)((w * 16 + rA) * VSTR + ks * 16 + kA) * 2;
        LDSM4(qh[ks], sbase + off);
        LDSM4(ql[ks], sbase + off + TILE_BYTES);
    }
    __syncthreads();

    float m0 = NEGINF, m1 = NEGINF, z0 = 0.0f, z1 = 0.0f;

    float4 pv[8];
    #pragma unroll
    for (int r = 0; r < 8; r++)
        pv[r] = *(const float4*)(Vg + (size_t)(r * 16 + ldq) * DD + ldd4);

    for (int c = 0; c < NCHUNK; c++) {
        char*    smb = smraw + (c & 1) * BUF_BYTES;
        uint32_t sb  = sbase + (c & 1) * BUF_BYTES;

        #pragma unroll
        for (int r = 0; r < 8; r++)
            split_store(smb, stoff + (uint32_t)(r * 16 * VSTR) * 2, pv[r]);
        __syncthreads();

        if (c + 1 < NCHUNK) {
            const float* vn = Vg + (size_t)((c + 1) * KT + ldq) * DD + ldd4;
            #pragma unroll
            for (int r = 0; r < 8; r++)
                pv[r] = *(const float4*)(vn + (size_t)(r * 16) * DD);
        }

        // ---- GEMM1: 3-combo fp16 split ----
        float sacc[16][4];
        #pragma unroll
        for (int j = 0; j < 16; j++)
            #pragma unroll
            for (int e = 0; e < 4; e++) sacc[j][e] = 0.0f;

        #pragma unroll
        for (int ks = 0; ks < 4; ks++) {
            #pragma unroll
            for (int np = 0; np < 8; np++) {
                uint32_t off = (uint32_t)((np * 16 + rB) * VSTR + ks * 16 + kB) * 2;
                uint32_t bh[4], bl[4];
                LDSM4(bh, sb + off);
                LDSM4(bl, sb + off + TILE_BYTES);
                mma16816(sacc[2 * np],     qh[ks], bh[0], bh[1]);
                mma16816(sacc[2 * np + 1], qh[ks], bh[2], bh[3]);
                mma16816(sacc[2 * np],     qh[ks], bl[0], bl[1]);
                mma16816(sacc[2 * np + 1], qh[ks], bl[2], bl[3]);
                mma16816(sacc[2 * np],     ql[ks], bh[0], bh[1]);
                mma16816(sacc[2 * np + 1], ql[ks], bh[2], bh[3]);
            }
        }

        // ---- raw scores out ----
        {
            float* srow0 = attn_out + (size_t)(b * SS + q0 + w * 16 + g) * SS + c * KT + 2 * p;
            float* srow1 = srow0 + (size_t)8 * SS;
            #pragma unroll
            for (int j = 0; j < 16; j++) {
                *(float2*)(srow0 + 8 * j) = make_float2(sacc[j][0], sacc[j][1]);
                *(float2*)(srow1 + 8 * j) = make_float2(sacc[j][2], sacc[j][3]);
            }
        }

        // ---- stats only (no P, no GEMM2) ----
        float ml0 = NEGINF, ml1 = NEGINF;
        #pragma unroll
        for (int j = 0; j < 16; j++) {
            ml0 = fmaxf(ml0, fmaxf(sacc[j][0], sacc[j][1]));
            ml1 = fmaxf(ml1, fmaxf(sacc[j][2], sacc[j][3]));
        }
        #pragma unroll
        for (int off = 1; off <= 2; off <<= 1) {
            ml0 = fmaxf(ml0, __shfl_xor_sync(0xffffffffu, ml0, off));
            ml1 = fmaxf(ml1, __shfl_xor_sync(0xffffffffu, ml1, off));
        }
        float mn0 = fmaxf(m0, ml0), mn1 = fmaxf(m1, ml1);
        float sc0 = __expf(m0 - mn0), sc1 = __expf(m1 - mn1);
        m0 = mn0; m1 = mn1;

        float s0 = 0.0f, s1 = 0.0f;
        #pragma unroll
        for (int j = 0; j < 16; j++) {
            s0 += __expf(sacc[j][0] - mn0) + __expf(sacc[j][1] - mn0);
            s1 += __expf(sacc[j][2] - mn1) + __expf(sacc[j][3] - mn1);
        }
        #pragma unroll
        for (int off = 1; off <= 2; off <<= 1) {
            s0 += __shfl_xor_sync(0xffffffffu, s0, off);
            s1 += __shfl_xor_sync(0xffffffffu, s1, off);
        }
        z0 = z0 * sc0 + s0;
        z1 = z1 * sc1 + s1;
        __syncthreads();
    }

    if (p == 0) {
        int row = b * SS + q0 + w * 16 + g;
        g_rowm[row]     = m0;
        g_rowz[row]     = z0;
        g_rowm[row + 8] = m1;
        g_rowz[row + 8] = z1;
    }
}

// ============ PASS 2: normalize weights in place + GEMM2 -> ctx ============
__global__ void __launch_bounds__(NTH, 1)
attn_pass2(const float* __restrict__ V, float* __restrict__ attn,
           float* __restrict__ ctx_out)
{
    extern __shared__ __align__(16) char smraw[];   // [wtile][vtile]
    char* wtile = smraw;                            // QT x WSTR fp16
    char* vtile = smraw + QT * WSTR * 2;            // KT x VSTR fp16

    const int tid  = threadIdx.x;
    const int w    = tid >> 5;
    const int lane = tid & 31;
    const int g    = lane >> 2;
    const int p    = lane & 3;
    const int b    = blockIdx.y;
    const int q0   = blockIdx.x * QT;

    const float* Vg = V + (size_t)b * SS * DD;
    float* Ag = attn + (size_t)(b * SS + q0) * SS;

    const uint32_t wbase = smem_u32(wtile);
    const uint32_t vbase = smem_u32(vtile);

    const int rowb = b * SS + q0 + w * 16;   // this warp's first global row

    // per-row stats (uniform across lanes)
    float mr[16], izr[16];
    #pragma unroll
    for (int i = 0; i < 16; i++) {
        mr[i]  = g_rowm[rowb + i];
        izr[i] = 1.0f / g_rowz[rowb + i];
    }

    const int rA = (lane & 7) + ((lane >> 3) & 1) * 8;
    const int kA = (lane >> 4) * 8;

    // V staging coords
    const int ldq  = tid >> 4;
    const int ldd4 = (tid & 15) * 4;

    float cacc[8][4];
    #pragma unroll
    for (int j = 0; j < 8; j++)
        #pragma unroll
        for (int e = 0; e < 4; e++) cacc[j][e] = 0.0f;

    // prefetch chunk 0: S rows (warp-owned) + V
    float4 spre[16];
    #pragma unroll
    for (int i = 0; i < 16; i++)
        spre[i] = *(const float4*)(Ag + (size_t)(w * 16 + i) * SS + lane * 4);
    float4 vpre[8];
    #pragma unroll
    for (int r = 0; r < 8; r++)
        vpre[r] = *(const float4*)(Vg + (size_t)(r * 16 + ldq) * DD + ldd4);

    for (int c = 0; c < NCHUNK; c++) {
        // ---- compute p = exp(s-m); write w = p*iz; stage p fp16 ----
        #pragma unroll
        for (int i = 0; i < 16; i++) {
            float m = mr[i], iz = izr[i];
            float4 s = spre[i];
            float p0 = __expf(s.x - m);
            float p1 = __expf(s.y - m);
            float p2 = __expf(s.z - m);
            float p3 = __expf(s.w - m);
            float4 wv = make_float4(p0 * iz, p1 * iz, p2 * iz, p3 * iz);
            __stcs((float4*)(Ag + (size_t)(w * 16 + i) * SS + c * KT + lane * 4), wv);
            *(uint2*)(wtile + ((w * 16 + i) * WSTR + lane * 4) * 2) =
                make_uint2(pack_f16(p0, p1), pack_f16(p2, p3));
        }
        // ---- stage V (hi fp16 only) ----
        #pragma unroll
        for (int r = 0; r < 8; r++) {
            float4 v = vpre[r];
            *(uint2*)(vtile + ((r * 16 + ldq) * VSTR + ldd4) * 2) =
                make_uint2(pack_f16(v.x, v.y), pack_f16(v.z, v.w));
        }
        __syncthreads();

        // ---- prefetch next chunk during MMA phase ----
        if (c + 1 < NCHUNK) {
            #pragma unroll
            for (int i = 0; i < 16; i++)
                spre[i] = *(const float4*)(Ag + (size_t)(w * 16 + i) * SS
                                           + (c + 1) * KT + lane * 4);
            const float* vn = Vg + (size_t)((c + 1) * KT + ldq) * DD + ldd4;
            #pragma unroll
            for (int r = 0; r < 8; r++)
                vpre[r] = *(const float4*)(vn + (size_t)(r * 16) * DD);
        }

        // ---- GEMM2: ctx += P(fp16) @ Vh ----
        #pragma unroll
        for (int kk = 0; kk < 8; kk++) {
            uint32_t aw[4];
            LDSM4(aw, wbase + (uint32_t)((w * 16 + rA) * WSTR + kk * 16 + kA) * 2);
            #pragma unroll
            for (int np = 0; np < 4; np++) {
                uint32_t bh[4];
                LDSM4T(bh, vbase + (uint32_t)((kk * 16 + rA) * VSTR + np * 16 + kA) * 2);
                mma16816(cacc[2 * np],     aw, bh[0], bh[1]);
                mma16816(cacc[2 * np + 1], aw, bh[2], bh[3]);
            }
        }
        __syncthreads();
    }

    // ---- epilogue: ctx = acc * iz ----
    const float iz0 = izr[g], iz1 = izr[g + 8];
    float* crow0 = ctx_out + (size_t)(rowb + g) * DD + 2 * p;
    float* crow1 = crow0 + (size_t)8 * DD;
    #pragma unroll
    for (int j = 0; j < 8; j++) {
        *(float2*)(crow0 + 8 * j) = make_float2(cacc[j][0] * iz0, cacc[j][1] * iz0);
        *(float2*)(crow1 + 8 * j) = make_float2(cacc[j][2] * iz1, cacc[j][3] * iz1);
    }
}

extern "C" void kernel_launch(void* const* d_in, const int* in_sizes, int n_in,
                              void* d_out, int out_size)
{
    const float* Q = (const float*)d_in[0];
    const float* V = (const float*)d_in[1];
    float* out  = (float*)d_out;
    float* ctx  = out;                           // [B, S, D]
    float* attn = out + (size_t)BB * SS * DD;    // [B, S, S]

    cudaFuncSetAttribute(attn_pass1,
                         cudaFuncAttributeMaxDynamicSharedMemorySize, SMEM_P1);
    cudaFuncSetAttribute(attn_pass2,
                         cudaFuncAttributeMaxDynamicSharedMemorySize, SMEM_P2);

    dim3 grid(SS / QT, BB);   // 32 x 4 = 128 CTAs
    attn_pass1<<<grid, NTH, SMEM_P1>>>(Q, V, attn);
    attn_pass2<<<grid, NTH, SMEM_P2>>>(V, attn, ctx);
}